// round 10
// baseline (speedup 1.0000x reference)
#include <cuda_runtime.h>

// Problem constants
#define Bc 4096
#define Tc 256
#define I1c 38
#define H1c 50
#define H2c 15
#define NCc 14

// Tiling: worker thread = (unit u, batch-half bh, k-half kh)
#define NB    32
#define NTH   288          // 9 warps: 260 workers + 28 prefetch
#define NWORK 260          // 65 units x 2 bh x 2 kh
#define NU    65
#define NUP   66           // padded unit pitch in weight table
#define KL    88           // padded dot length (L2 zero-padded)
#define KL2   65
#define VPF   36           // v row pitch (floats): 144 B
#define VROWS 128          // [0,38)=x, [38,88)=h1, [88,103)=h2, rest zero
#define VSZ   (VROWS*VPF)

// Weight table: ulonglong2 wq[(k*2+gp)*NUP + u]
//   gp=0 -> {(wi,wi),(wf,wf)}, gp=1 -> {(wg,wg),(wo,wo)}
#define WQ_N       (KL*2*NUP)            // 11616 * 16 B = 185856 B
#define SM_V_BYTE  (WQ_N*16)
#define SMEM_BYTES (SM_V_BYTE + 2*VSZ*4) // 222720 B

typedef unsigned long long u64t;

__device__ __forceinline__ u64t pk2(float a, float b){
    u64t d; asm("mov.b64 %0, {%1, %2};" : "=l"(d) : "f"(a), "f"(b)); return d;
}
__device__ __forceinline__ void up2(u64t d, float& a, float& b){
    asm("mov.b64 {%0, %1}, %2;" : "=f"(a), "=f"(b) : "l"(d));
}
__device__ __forceinline__ void fma2(u64t& d, u64t a, u64t b){
    asm("fma.rn.f32x2 %0, %1, %2, %0;" : "+l"(d) : "l"(a), "l"(b));
}
__device__ __forceinline__ u64t add2(u64t a, u64t b){
    u64t d; asm("add.rn.f32x2 %0, %1, %2;" : "=l"(d) : "l"(a), "l"(b)); return d;
}

__device__ __forceinline__ float sigf(float x){
    float e = __expf(-x);
    return __fdividef(1.0f, 1.0f + e);
}
__device__ __forceinline__ float tanh_(float x){
    float a = fabsf(x);
    float e = __expf(-2.0f * a);
    float r = __fdividef(1.0f - e, 1.0f + e);
    return copysignf(r, x);
}

// Unified-row weight fetch. u<50: L1 unit (window [x|h1], base 0).
// 50<=u<65: L2 unit r (window [h1|h2|pad], base 38). u==65: pad column.
__device__ __forceinline__ float wfetch(int u, int g, int k,
    const float* __restrict__ w_ih1, const float* __restrict__ w_hh1,
    const float* __restrict__ w_ih2, const float* __restrict__ w_hh2)
{
    if (u < 50){
        int row = g * H1c + u;
        return (k < I1c) ? w_ih1[row*I1c + k] : w_hh1[row*H1c + (k - I1c)];
    } else if (u < NU){
        int r = u - 50, row = g * H2c + r;
        if (k < H1c)      return w_ih2[row*H1c + k];
        else if (k < KL2) return w_hh2[row*H2c + (k - H1c)];
    }
    return 0.0f;
}

__global__ __launch_bounds__(NTH, 1)
void lstm_persist_kernel(const float* __restrict__ x,
                         const float* __restrict__ w_ih1, const float* __restrict__ w_hh1,
                         const float* __restrict__ b_ih1, const float* __restrict__ b_hh1,
                         const float* __restrict__ w_ih2, const float* __restrict__ w_hh2,
                         const float* __restrict__ b_ih2, const float* __restrict__ b_hh2,
                         const float* __restrict__ w_fc,  const float* __restrict__ b_fc,
                         float* __restrict__ out)
{
    extern __shared__ char smc[];
    ulonglong2* wq   = reinterpret_cast<ulonglong2*>(smc);
    float*      vbuf = reinterpret_cast<float*>(smc + SM_V_BYTE);

    const int tid = threadIdx.x;
    const int b0  = blockIdx.x * NB;

    // ---- Build gate-packed duplicated weight table ----
    for (int idx = tid; idx < WQ_N; idx += NTH){
        int u  = idx % NUP;
        int t2 = idx / NUP;          // k*2 + gp
        int gp = t2 & 1, k = t2 >> 1;
        float wa = wfetch(u, gp*2,     k, w_ih1, w_hh1, w_ih2, w_hh2);
        float wb = wfetch(u, gp*2 + 1, k, w_ih1, w_hh1, w_ih2, w_hh2);
        ulonglong2 e; e.x = pk2(wa, wa); e.y = pk2(wb, wb);
        wq[idx] = e;
    }

    // ---- Zero both v buffers (incl. pad rows), then load x(0) ----
    for (int idx = tid; idx < 2*VSZ; idx += NTH) vbuf[idx] = 0.0f;
    __syncthreads();
    for (int idx = tid; idx < NB*I1c; idx += NTH){
        int nb = idx / I1c, i = idx % I1c;
        vbuf[i*VPF + nb] = x[((size_t)(b0 + nb) * Tc) * I1c + i];
    }

    // Worker roles
    const int u  = tid >> 2;        // unit 0..64 (tid<260)
    const int bh = (tid >> 1) & 1;  // batch half (16 each)
    const int kh = tid & 1;         // k parity
    const bool isL1 = (u < 50);
    const bool work = (tid < NWORK);
    const unsigned pmask = 0x3u << ((tid & 31) & ~1);  // exact pair mask

    // Only kh==0 carries bias (pair-combine would double it)
    float bI=0, bF=0, bG=0, bO=0;
    if (work && kh == 0){
        if (isL1){
            bI = b_ih1[0*H1c+u] + b_hh1[0*H1c+u];
            bF = b_ih1[1*H1c+u] + b_hh1[1*H1c+u];
            bG = b_ih1[2*H1c+u] + b_hh1[2*H1c+u];
            bO = b_ih1[3*H1c+u] + b_hh1[3*H1c+u];
        } else {
            int r = u - 50;
            bI = b_ih2[0*H2c+r] + b_hh2[0*H2c+r];
            bF = b_ih2[1*H2c+r] + b_hh2[1*H2c+r];
            bG = b_ih2[2*H2c+r] + b_hh2[2*H2c+r];
            bO = b_ih2[3*H2c+r] + b_hh2[3*H2c+r];
        }
    }

    // Cell state: this thread's kept 8 batches = bh*16 + kh*8 + 0..7
    float cst[8];
    #pragma unroll
    for (int s = 0; s < 8; s++) cst[s] = 0.0f;

    const int base = isL1 ? 0 : I1c;
    const int hrow = isL1 ? (I1c + u) : (88 + (u - 50));
    __syncthreads();

    // Iter t: L1 computes step t (x(t), h1(t-1)); L2 computes step t-1.
    for (int t = 0; t <= Tc; t++){
        float* vc = vbuf + (t & 1) * VSZ;
        float* vn = vbuf + ((t + 1) & 1) * VSZ;

        if (work){
            // acc[g][p]: gate g, f32x2 pair p covers batches bh*16 + 2p,2p+1
            u64t aI[8], aF[8], aG[8], aO[8];
            #pragma unroll
            for (int p = 0; p < 8; p++){
                aI[p] = pk2(bI,bI); aF[p] = pk2(bF,bF);
                aG[p] = pk2(bG,bG); aO[p] = pk2(bO,bO);
            }

            // own k = 2j + kh, j = 0..43
            const ulonglong2* wr = wq + (size_t)(2*kh)*NUP + u;
            const float*      vp = vc + (base + kh)*VPF + bh*16;
            #pragma unroll 2
            for (int j = 0; j < 44; j++){
                ulonglong2 wa = wr[(size_t)j*4*NUP];        // (wi,wi),(wf,wf)
                ulonglong2 wb = wr[(size_t)j*4*NUP + NUP];  // (wg,wg),(wo,wo)
                const ulonglong2* vq = reinterpret_cast<const ulonglong2*>(vp + j*2*VPF);
                ulonglong2 q0 = vq[0], q1 = vq[1], q2 = vq[2], q3 = vq[3];
                fma2(aI[0], wa.x, q0.x); fma2(aI[1], wa.x, q0.y);
                fma2(aI[2], wa.x, q1.x); fma2(aI[3], wa.x, q1.y);
                fma2(aI[4], wa.x, q2.x); fma2(aI[5], wa.x, q2.y);
                fma2(aI[6], wa.x, q3.x); fma2(aI[7], wa.x, q3.y);
                fma2(aF[0], wa.y, q0.x); fma2(aF[1], wa.y, q0.y);
                fma2(aF[2], wa.y, q1.x); fma2(aF[3], wa.y, q1.y);
                fma2(aF[4], wa.y, q2.x); fma2(aF[5], wa.y, q2.y);
                fma2(aF[6], wa.y, q3.x); fma2(aF[7], wa.y, q3.y);
                fma2(aG[0], wb.x, q0.x); fma2(aG[1], wb.x, q0.y);
                fma2(aG[2], wb.x, q1.x); fma2(aG[3], wb.x, q1.y);
                fma2(aG[4], wb.x, q2.x); fma2(aG[5], wb.x, q2.y);
                fma2(aG[6], wb.x, q3.x); fma2(aG[7], wb.x, q3.y);
                fma2(aO[0], wb.y, q0.x); fma2(aO[1], wb.y, q0.y);
                fma2(aO[2], wb.y, q1.x); fma2(aO[3], wb.y, q1.y);
                fma2(aO[4], wb.y, q2.x); fma2(aO[5], wb.y, q2.y);
                fma2(aO[6], wb.y, q3.x); fma2(aO[7], wb.y, q3.y);
            }

            // Pair combine over kh (UNCONDITIONAL; both lanes run the same
            // shuffle sequence). kh=0 keeps pairs 0..3, sends 4..7; kh=1 the
            // reverse. fin[g][q] = gate sums for batches bh*16 + kh*8 + 2q,2q+1.
            u64t fI[4], fF[4], fG[4], fO[4];
            #pragma unroll
            for (int q = 0; q < 4; q++){
                u64t sI = kh ? aI[q] : aI[q+4];
                u64t oI = kh ? aI[q+4] : aI[q];
                fI[q] = add2(oI, __shfl_xor_sync(pmask, sI, 1));
                u64t sF = kh ? aF[q] : aF[q+4];
                u64t oF = kh ? aF[q+4] : aF[q];
                fF[q] = add2(oF, __shfl_xor_sync(pmask, sF, 1));
                u64t sG = kh ? aG[q] : aG[q+4];
                u64t oG = kh ? aG[q+4] : aG[q];
                fG[q] = add2(oG, __shfl_xor_sync(pmask, sG, 1));
                u64t sO = kh ? aO[q] : aO[q+4];
                u64t oO = kh ? aO[q+4] : aO[q];
                fO[q] = add2(oO, __shfl_xor_sync(pmask, sO, 1));
            }

            if (isL1 ? (t < Tc) : (t >= 1)){
                float hv[8];
                #pragma unroll
                for (int q = 0; q < 4; q++){
                    float i0,i1,f0,f1,g0,g1,o0,o1;
                    up2(fI[q], i0, i1);
                    up2(fF[q], f0, f1);
                    up2(fG[q], g0, g1);
                    up2(fO[q], o0, o1);
                    float c0 = fmaf(sigf(f0), cst[2*q  ], sigf(i0)*tanh_(g0));
                    float c1 = fmaf(sigf(f1), cst[2*q+1], sigf(i1)*tanh_(g1));
                    cst[2*q  ] = c0;
                    cst[2*q+1] = c1;
                    hv[2*q  ] = sigf(o0)*tanh_(c0);
                    hv[2*q+1] = sigf(o1)*tanh_(c1);
                }
                float* hd = vn + hrow*VPF + bh*16 + kh*8;
                *reinterpret_cast<float4*>(hd)     = make_float4(hv[0],hv[1],hv[2],hv[3]);
                *reinterpret_cast<float4*>(hd + 4) = make_float4(hv[4],hv[5],hv[6],hv[7]);
            }
        } else {
            // ---- Prefetch threads (tid 260..287): x(t+1) -> vn rows [0,38) ----
            if (t + 1 < Tc){
                int pt = tid - NWORK;
                for (int idx = pt; idx < NB*I1c; idx += (NTH - NWORK)){
                    int nb = idx / I1c, i = idx % I1c;
                    vn[i*VPF + nb] =
                        __ldcg(x + ((size_t)(b0 + nb) * Tc + (t + 1)) * I1c + i);
                }
            }
        }
        __syncthreads();
    }

    // ---- FC head: final h2 in vbuf[1] rows 88..102 ----
    const float* h2f = vbuf + VSZ + 88*VPF;
    for (int q = tid; q < NB*NCc; q += NTH){
        int nb = q / NCc, cls = q % NCc;
        float s = b_fc[cls];
        #pragma unroll
        for (int h = 0; h < H2c; h++)
            s = fmaf(w_fc[cls*H2c + h], h2f[h*VPF + nb], s);
        out[(size_t)(b0 + nb)*NCc + cls] = s;
    }
}

extern "C" void kernel_launch(void* const* d_in, const int* in_sizes, int n_in,
                              void* d_out, int out_size)
{
    const float* x     = (const float*)d_in[0];
    const float* w_ih1 = (const float*)d_in[1];
    const float* w_hh1 = (const float*)d_in[2];
    const float* b_ih1 = (const float*)d_in[3];
    const float* b_hh1 = (const float*)d_in[4];
    const float* w_ih2 = (const float*)d_in[5];
    const float* w_hh2 = (const float*)d_in[6];
    const float* b_ih2 = (const float*)d_in[7];
    const float* b_hh2 = (const float*)d_in[8];
    const float* w_fc  = (const float*)d_in[9];
    const float* b_fc  = (const float*)d_in[10];
    float* out = (float*)d_out;

    cudaFuncSetAttribute(lstm_persist_kernel,
                         cudaFuncAttributeMaxDynamicSharedMemorySize, SMEM_BYTES);

    const int grid = Bc / NB;   // 128 CTAs -> one wave
    lstm_persist_kernel<<<grid, NTH, SMEM_BYTES>>>(
        x, w_ih1, w_hh1, b_ih1, b_hh1,
        w_ih2, w_hh2, b_ih2, b_hh2, w_fc, b_fc, out);
}

// round 11
// speedup vs baseline: 1.7803x; 1.7803x over previous
#include <cuda_runtime.h>

// Problem constants
#define Bc 4096
#define Tc 256
#define I1c 38
#define H1c 50
#define H2c 15
#define NCc 14

// Tiling (R8 geometry: thread = (unit u, cg in 4 -> 8 batch, kh in 2))
#define NB    32
#define NTH   576          // 18 warps
#define NWORK 520          // 65 units x 4 cg x 2 kh
#define NU    65
#define NUP   66           // padded unit pitch
#define KL    88           // padded dot length (L2 zero-padded)
#define KL2   65
#define VPF   36           // v row pitch in floats (144 B)
#define VROWS 128          // [0,38)=x, [38,88)=h1, [88,103)=h2, rest zero
#define VSZ   (VROWS*VPF)

// Weight table: ulonglong2 wq[(k*2+gp)*NUP + u]
//   gp=0 -> {(wi,wi),(wf,wf)}, gp=1 -> {(wg,wg),(wo,wo)}
#define WQ_N          (KL*2*NUP)
#define SM_V_BYTE     (WQ_N*16)
#define SM_STAGE_BYTE (SM_V_BYTE + 2*VSZ*4)
#define STAGE_PITCH   41
#define SMEM_BYTES    (SM_STAGE_BYTE + 32*STAGE_PITCH*4)  // 227968 B

typedef unsigned long long u64t;

__device__ __forceinline__ u64t pk2(float a, float b){
    u64t d; asm("mov.b64 %0, {%1, %2};" : "=l"(d) : "f"(a), "f"(b)); return d;
}
__device__ __forceinline__ void up2(u64t d, float& a, float& b){
    asm("mov.b64 {%0, %1}, %2;" : "=f"(a), "=f"(b) : "l"(d));
}
__device__ __forceinline__ void fma2(u64t& d, u64t a, u64t b){
    asm("fma.rn.f32x2 %0, %1, %2, %0;" : "+l"(d) : "l"(a), "l"(b));
}
__device__ __forceinline__ u64t add2(u64t a, u64t b){
    u64t d; asm("add.rn.f32x2 %0, %1, %2;" : "=l"(d) : "l"(a), "l"(b)); return d;
}

// MUFU.TANH-based activations (sm_75+ tanh.approx.f32)
__device__ __forceinline__ float tanha(float x){
    float r; asm("tanh.approx.f32 %0, %1;" : "=f"(r) : "f"(x)); return r;
}
__device__ __forceinline__ float sigf(float x){
    return fmaf(0.5f, tanha(0.5f * x), 0.5f);
}

// Unified-row weight fetch. u<50: L1 unit (window [x|h1], base 0).
// 50<=u<65: L2 unit r (window [h1|h2|pad], base 38). u==65: pad column.
__device__ __forceinline__ float wfetch(int u, int g, int k,
    const float* __restrict__ w_ih1, const float* __restrict__ w_hh1,
    const float* __restrict__ w_ih2, const float* __restrict__ w_hh2)
{
    if (u < 50){
        int row = g * H1c + u;
        return (k < I1c) ? w_ih1[row*I1c + k] : w_hh1[row*H1c + (k - I1c)];
    } else if (u < NU){
        int r = u - 50, row = g * H2c + r;
        if (k < H1c)      return w_ih2[row*H1c + k];
        else if (k < KL2) return w_hh2[row*H2c + (k - H1c)];
    }
    return 0.0f;
}

__global__ __launch_bounds__(NTH, 1)
void lstm_persist_kernel(const float* __restrict__ x,
                         const float* __restrict__ w_ih1, const float* __restrict__ w_hh1,
                         const float* __restrict__ b_ih1, const float* __restrict__ b_hh1,
                         const float* __restrict__ w_ih2, const float* __restrict__ w_hh2,
                         const float* __restrict__ b_ih2, const float* __restrict__ b_hh2,
                         const float* __restrict__ w_fc,  const float* __restrict__ b_fc,
                         float* __restrict__ out)
{
    extern __shared__ char smc[];
    ulonglong2* wq   = reinterpret_cast<ulonglong2*>(smc);
    float*      vbuf = reinterpret_cast<float*>(smc + SM_V_BYTE);
    float*      stg  = reinterpret_cast<float*>(smc + SM_STAGE_BYTE);

    const int tid = threadIdx.x;
    const int b0  = blockIdx.x * NB;

    // ---- Build gate-packed duplicated weight table ----
    for (int idx = tid; idx < WQ_N; idx += NTH){
        int u  = idx % NUP;
        int t2 = idx / NUP;
        int gp = t2 & 1, k = t2 >> 1;
        float wa = wfetch(u, gp*2,     k, w_ih1, w_hh1, w_ih2, w_hh2);
        float wb = wfetch(u, gp*2 + 1, k, w_ih1, w_hh1, w_ih2, w_hh2);
        ulonglong2 e; e.x = pk2(wa, wa); e.y = pk2(wb, wb);
        wq[idx] = e;
    }

    // ---- Zero both v buffers (incl. pad rows), then load x(0) ----
    for (int idx = tid; idx < 2*VSZ; idx += NTH) vbuf[idx] = 0.0f;
    __syncthreads();
    for (int idx = tid; idx < NB*I1c; idx += NTH){
        int nb = idx / I1c, i = idx % I1c;
        vbuf[i*VPF + nb] = x[((size_t)(b0 + nb) * Tc) * I1c + i];
    }

    // Worker roles
    const int u  = tid >> 3;
    const int cg = (tid >> 1) & 3;
    const int kh = tid & 1;
    const bool isL1 = (u < 50);
    const bool work = (tid < NWORK);
    const unsigned pmask = 0x3u << ((tid & 31) & ~1);  // exact pair mask

    float bI=0, bF=0, bG=0, bO=0;
    if (work && kh == 0){   // only kh=0 carries bias
        if (isL1){
            bI = b_ih1[0*H1c+u] + b_hh1[0*H1c+u];
            bF = b_ih1[1*H1c+u] + b_hh1[1*H1c+u];
            bG = b_ih1[2*H1c+u] + b_hh1[2*H1c+u];
            bO = b_ih1[3*H1c+u] + b_hh1[3*H1c+u];
        } else {
            int r = u - 50;
            bI = b_ih2[0*H2c+r] + b_hh2[0*H2c+r];
            bF = b_ih2[1*H2c+r] + b_hh2[1*H2c+r];
            bG = b_ih2[2*H2c+r] + b_hh2[2*H2c+r];
            bO = b_ih2[3*H2c+r] + b_hh2[3*H2c+r];
        }
    }

    float cst[4];   // this thread's 4 batches: cg*8 + kh*4 + 0..3
    #pragma unroll
    for (int s = 0; s < 4; s++) cst[s] = 0.0f;

    const int base = isL1 ? 0 : I1c;
    const int hrow = isL1 ? (I1c + u) : (88 + (u - 50));
    __syncthreads();

    // Iter t: L1 computes step t (x(t), h1(t-1)); L2 computes step t-1.
    for (int t = 0; t <= Tc; t++){
        float* vc = vbuf + (t & 1) * VSZ;
        float* vn = vbuf + ((t + 1) & 1) * VSZ;

        if (work){
            u64t aI[4], aF[4], aG[4], aO[4];
            #pragma unroll
            for (int p = 0; p < 4; p++){
                aI[p] = pk2(bI,bI); aF[p] = pk2(bF,bF);
                aG[p] = pk2(bG,bG); aO[p] = pk2(bO,bO);
            }

            // own k = 2j + kh, j = 0..43 — FULL unroll: all LDS offsets
            // become immediates, no per-iteration address arithmetic.
            const ulonglong2* wr = wq + (size_t)(2*kh)*NUP + u;
            const float*      vp = vc + (base + kh)*VPF + cg*8;
            #pragma unroll
            for (int j = 0; j < 44; j++){
                ulonglong2 wa = wr[(size_t)j*4*NUP];        // (wi,wi),(wf,wf)
                ulonglong2 wb = wr[(size_t)j*4*NUP + NUP];  // (wg,wg),(wo,wo)
                ulonglong2 v0 = *reinterpret_cast<const ulonglong2*>(vp + j*2*VPF);
                ulonglong2 v1 = *reinterpret_cast<const ulonglong2*>(vp + j*2*VPF + 4);
                fma2(aI[0], wa.x, v0.x); fma2(aI[1], wa.x, v0.y);
                fma2(aI[2], wa.x, v1.x); fma2(aI[3], wa.x, v1.y);
                fma2(aF[0], wa.y, v0.x); fma2(aF[1], wa.y, v0.y);
                fma2(aF[2], wa.y, v1.x); fma2(aF[3], wa.y, v1.y);
                fma2(aG[0], wb.x, v0.x); fma2(aG[1], wb.x, v0.y);
                fma2(aG[2], wb.x, v1.x); fma2(aG[3], wb.x, v1.y);
                fma2(aO[0], wb.y, v0.x); fma2(aO[1], wb.y, v0.y);
                fma2(aO[2], wb.y, v1.x); fma2(aO[3], wb.y, v1.y);
            }

            // Combine k-halves UNCONDITIONALLY (deadlock-safe: both pair
            // lanes always execute identical shuffle sequences).
            #pragma unroll
            for (int p = 0; p < 4; p++){
                aI[p] = add2(aI[p], __shfl_xor_sync(pmask, aI[p], 1));
                aF[p] = add2(aF[p], __shfl_xor_sync(pmask, aF[p], 1));
                aG[p] = add2(aG[p], __shfl_xor_sync(pmask, aG[p], 1));
                aO[p] = add2(aO[p], __shfl_xor_sync(pmask, aO[p], 1));
            }

            if (isL1 ? (t < Tc) : (t >= 1)){
                int p0 = 2*kh, p1 = 2*kh + 1;
                float i0,i1,i2,i3, f0,f1,f2,f3, g0,g1,g2,g3, o0,o1,o2,o3;
                up2(aI[p0], i0, i1); up2(aI[p1], i2, i3);
                up2(aF[p0], f0, f1); up2(aF[p1], f2, f3);
                up2(aG[p0], g0, g1); up2(aG[p1], g2, g3);
                up2(aO[p0], o0, o1); up2(aO[p1], o2, o3);
                float c0 = fmaf(sigf(f0), cst[0], sigf(i0)*tanha(g0));
                float c1 = fmaf(sigf(f1), cst[1], sigf(i1)*tanha(g1));
                float c2 = fmaf(sigf(f2), cst[2], sigf(i2)*tanha(g2));
                float c3 = fmaf(sigf(f3), cst[3], sigf(i3)*tanha(g3));
                cst[0]=c0; cst[1]=c1; cst[2]=c2; cst[3]=c3;
                float4 hv;
                hv.x = sigf(o0)*tanha(c0);
                hv.y = sigf(o1)*tanha(c1);
                hv.z = sigf(o2)*tanha(c2);
                hv.w = sigf(o3)*tanha(c3);
                *reinterpret_cast<float4*>(vn + hrow*VPF + cg*8 + kh*4) = hv;
            }
        } else if (tid >= 544){
            // ---- Prefetch warp: coalesced load of x(t+1), staged transpose ----
            int lane = tid - 544;
            if (t + 1 < Tc){
                #pragma unroll 4
                for (int r = 0; r < NB; r++){
                    const float* xs = x + ((size_t)(b0 + r) * Tc + (t + 1)) * I1c;
                    stg[r*STAGE_PITCH + lane] = __ldcg(xs + lane);
                    if (lane < I1c - 32)
                        stg[r*STAGE_PITCH + 32 + lane] = __ldcg(xs + 32 + lane);
                }
                __syncwarp();
                #pragma unroll
                for (int i = 0; i < I1c; i++)
                    vn[i*VPF + lane] = stg[lane*STAGE_PITCH + i];
            }
        }
        __syncthreads();
    }

    // ---- FC head: final h2 in vbuf[1] rows 88..102 ----
    const float* h2f = vbuf + VSZ + 88*VPF;
    for (int q = tid; q < NB*NCc; q += NTH){
        int nb = q / NCc, cls = q % NCc;
        float s = b_fc[cls];
        #pragma unroll
        for (int h = 0; h < H2c; h++)
            s = fmaf(w_fc[cls*H2c + h], h2f[h*VPF + nb], s);
        out[(size_t)(b0 + nb)*NCc + cls] = s;
    }
}

extern "C" void kernel_launch(void* const* d_in, const int* in_sizes, int n_in,
                              void* d_out, int out_size)
{
    const float* x     = (const float*)d_in[0];
    const float* w_ih1 = (const float*)d_in[1];
    const float* w_hh1 = (const float*)d_in[2];
    const float* b_ih1 = (const float*)d_in[3];
    const float* b_hh1 = (const float*)d_in[4];
    const float* w_ih2 = (const float*)d_in[5];
    const float* w_hh2 = (const float*)d_in[6];
    const float* b_ih2 = (const float*)d_in[7];
    const float* b_hh2 = (const float*)d_in[8];
    const float* w_fc  = (const float*)d_in[9];
    const float* b_fc  = (const float*)d_in[10];
    float* out = (float*)d_out;

    cudaFuncSetAttribute(lstm_persist_kernel,
                         cudaFuncAttributeMaxDynamicSharedMemorySize, SMEM_BYTES);

    const int grid = Bc / NB;   // 128 CTAs -> one wave
    lstm_persist_kernel<<<grid, NTH, SMEM_BYTES>>>(
        x, w_ih1, w_hh1, b_ih1, b_hh1,
        w_ih2, w_hh2, b_ih2, b_hh2, w_fc, b_fc, out);
}